// round 15
// baseline (speedup 1.0000x reference)
#include <cuda_runtime.h>
#include <cuda_bf16.h>
#include <cstdint>
#include <cmath>

typedef unsigned long long ull;

#define NB   8
#define NI   8192
#define IDIM 180
#define ADIM 1536
#define SDIM 1536
#define NS   64

// ----------------------------- device scratch -------------------------------
__device__ float g_Mpart[8 * IDIM * ADIM];
__device__ float g_Tpart[128 * IDIM * NS];
__device__ float g_Tt[NB * NS * IDIM];
__device__ float g_Gpart[128 * NS * NS];
__device__ float g_G[NB * NS * NS];
__device__ float g_m[NB * NS];
__device__ float g_stats[2 * NB * NI];
__device__ __align__(16) __nv_bfloat16 g_sThi[NB * SDIM * NS];   // slots^T hi [b][d][s]
__device__ __align__(16) __nv_bfloat16 g_sTlo[NB * SDIM * NS];   // slots^T lo
__device__ __align__(16) __nv_bfloat16 g_whi[NB * NI * NS];      // w hi [b][i][s]
__device__ __align__(16) __nv_bfloat16 g_wlo[NB * NI * NS];      // w lo

// ----------------------------- warp helpers ---------------------------------
__device__ __forceinline__ float wsum(float v) {
    #pragma unroll
    for (int o = 16; o > 0; o >>= 1) v += __shfl_xor_sync(0xffffffffu, v, o);
    return v;
}
__device__ __forceinline__ float wmax(float v) {
    #pragma unroll
    for (int o = 16; o > 0; o >>= 1) v = fmaxf(v, __shfl_xor_sync(0xffffffffu, v, o));
    return v;
}
__device__ __forceinline__ uint32_t smem_u32(const void* p) {
    uint32_t a;
    asm("{ .reg .u64 t; cvta.to.shared.u64 t, %1; cvt.u32.u64 %0, t; }" : "=r"(a) : "l"(p));
    return a;
}

// ----------------------------- f32x2 helpers ---------------------------------
__device__ __forceinline__ ull fma2(ull a, ull b, ull c) {
    ull d;
    asm("fma.rn.f32x2 %0, %1, %2, %3;" : "=l"(d) : "l"(a), "l"(b), "l"(c));
    return d;
}
__device__ __forceinline__ float2 unpack2(ull u) {
    float lo, hi;
    asm("mov.b64 {%0, %1}, %2;" : "=f"(lo), "=f"(hi) : "l"(u));
    return make_float2(lo, hi);
}

// --------------------------- mma.sync helpers --------------------------------
__device__ __forceinline__ void ldm_x4(uint32_t a, uint32_t* r) {
    asm volatile("ldmatrix.sync.aligned.m8n8.x4.shared.b16 {%0,%1,%2,%3}, [%4];"
        : "=r"(r[0]), "=r"(r[1]), "=r"(r[2]), "=r"(r[3]) : "r"(a));
}
__device__ __forceinline__ void mma_bf16(float* c, const uint32_t* a, const uint32_t* b) {
    asm volatile("mma.sync.aligned.m16n8k16.row.col.f32.bf16.bf16.f32 "
        "{%0,%1,%2,%3}, {%4,%5,%6,%7}, {%8,%9}, {%0,%1,%2,%3};"
        : "+f"(c[0]), "+f"(c[1]), "+f"(c[2]), "+f"(c[3])
        : "r"(a[0]), "r"(a[1]), "r"(a[2]), "r"(a[3]), "r"(b[0]), "r"(b[1]));
}

// ----------------------- shared GEMM tile body (NT) --------------------------
__device__ __forceinline__ void gemm_body(
    const float* __restrict__ A, const float* __restrict__ B, float* __restrict__ Cp,
    int M, int N, int Kchunk, int lda, int ldb, int m0, int n0,
    float (*As)[68], float (*Bs)[68])
{
    int tid = threadIdx.x;
    int tr = tid >> 4, tc = tid & 15;
    int lr = tid >> 2, lq = tid & 3;

    float acc[4][4] = {};

    for (int kb = 0; kb < Kchunk; kb += 16) {
        __syncthreads();
        float4 av = make_float4(0.f, 0.f, 0.f, 0.f);
        if (m0 + lr < M)
            av = *(const float4*)&A[(long long)(m0 + lr) * lda + kb + 4 * lq];
        As[4 * lq + 0][lr] = av.x; As[4 * lq + 1][lr] = av.y;
        As[4 * lq + 2][lr] = av.z; As[4 * lq + 3][lr] = av.w;
        float4 bv = make_float4(0.f, 0.f, 0.f, 0.f);
        if (n0 + lr < N)
            bv = *(const float4*)&B[(long long)(n0 + lr) * ldb + kb + 4 * lq];
        Bs[4 * lq + 0][lr] = bv.x; Bs[4 * lq + 1][lr] = bv.y;
        Bs[4 * lq + 2][lr] = bv.z; Bs[4 * lq + 3][lr] = bv.w;
        __syncthreads();
        #pragma unroll
        for (int k = 0; k < 16; ++k) {
            float4 a4 = *(const float4*)&As[k][4 * tr];
            float4 b4 = *(const float4*)&Bs[k][4 * tc];
            float a[4] = {a4.x, a4.y, a4.z, a4.w};
            float b[4] = {b4.x, b4.y, b4.z, b4.w};
            #pragma unroll
            for (int i = 0; i < 4; ++i)
                #pragma unroll
                for (int j = 0; j < 4; ++j)
                    acc[i][j] = fmaf(a[i], b[j], acc[i][j]);
        }
    }
    #pragma unroll
    for (int i = 0; i < 4; ++i)
        #pragma unroll
        for (int j = 0; j < 4; ++j) {
            int m = m0 + 4 * tr + i, n = n0 + 4 * tc + j;
            if (m < M && n < N) Cp[(long long)m * N + n] = acc[i][j];
        }
}

// ------------- fused M + G partial GEMMs (independent, one launch) ----------
__global__ void __launch_bounds__(256) gemm_MG(
    const float* __restrict__ Wq, const float* __restrict__ Wk,
    const float* __restrict__ slots)
{
    __shared__ __align__(16) float As[16][68];
    __shared__ __align__(16) float Bs[16][68];
    int bx = blockIdx.x;
    if (bx < 576) {
        int kk = bx & 7;
        int rem = bx >> 3;
        int mx = rem % 3, ny = rem / 3;
        gemm_body(Wq + kk * (ADIM / 8), Wk + kk * (ADIM / 8),
                  g_Mpart + (long long)kk * IDIM * ADIM,
                  IDIM, ADIM, ADIM / 8, ADIM, ADIM, mx * 64, ny * 64, As, Bs);
    } else {
        int z = bx - 576;
        int kk = z & 15, b = z >> 4;
        const float* sb = slots + (long long)b * NS * SDIM + kk * (SDIM / 16);
        gemm_body(sb, sb, g_Gpart + (long long)z * NS * NS,
                  NS, NS, SDIM / 16, SDIM, SDIM, 0, 0, As, Bs);
    }
}

// ---- T[b] = M @ slots^T (M summed inline from Mpart) + slot means + split --
__global__ void __launch_bounds__(256) gemm_T_aux(const float* __restrict__ slots)
{
    __shared__ __align__(16) char shbuf[33024];
    int bx = blockIdx.x;
    int tid = threadIdx.x;

    if (bx < 384) {
        int mx = bx % 3;
        int z = bx / 3;
        int kk = z & 15, b = z >> 4;
        int m0 = mx * 64;
        const float* B = slots + (long long)b * NS * SDIM + kk * (SDIM / 16);
        float* Cp = g_Tpart + (long long)z * IDIM * NS;
        float (*As)[68] = (float(*)[68])shbuf;
        float (*Bs)[68] = (float(*)[68])(shbuf + 4352);

        int tr = tid >> 4, tc = tid & 15;
        int lr = tid >> 2, lq = tid & 3;
        float acc[4][4] = {};

        for (int kb = 0; kb < SDIM / 16; kb += 16) {
            __syncthreads();
            float4 av = make_float4(0.f, 0.f, 0.f, 0.f);
            if (m0 + lr < IDIM) {
                const float* base = g_Mpart + (long long)(m0 + lr) * ADIM
                                  + kk * (SDIM / 16) + kb + 4 * lq;
                #pragma unroll
                for (int p = 0; p < 8; ++p) {
                    float4 v = *(const float4*)(base + (long long)p * IDIM * ADIM);
                    av.x += v.x; av.y += v.y; av.z += v.z; av.w += v.w;
                }
            }
            As[4 * lq + 0][lr] = av.x; As[4 * lq + 1][lr] = av.y;
            As[4 * lq + 2][lr] = av.z; As[4 * lq + 3][lr] = av.w;
            float4 bv = *(const float4*)&B[(long long)lr * SDIM + kb + 4 * lq];
            Bs[4 * lq + 0][lr] = bv.x; Bs[4 * lq + 1][lr] = bv.y;
            Bs[4 * lq + 2][lr] = bv.z; Bs[4 * lq + 3][lr] = bv.w;
            __syncthreads();
            #pragma unroll
            for (int k = 0; k < 16; ++k) {
                float4 a4 = *(const float4*)&As[k][4 * tr];
                float4 b4 = *(const float4*)&Bs[k][4 * tc];
                float a[4] = {a4.x, a4.y, a4.z, a4.w};
                float b[4] = {b4.x, b4.y, b4.z, b4.w};
                #pragma unroll
                for (int i = 0; i < 4; ++i)
                    #pragma unroll
                    for (int j = 0; j < 4; ++j)
                        acc[i][j] = fmaf(a[i], b[j], acc[i][j]);
            }
        }
        #pragma unroll
        for (int i = 0; i < 4; ++i)
            #pragma unroll
            for (int j = 0; j < 4; ++j) {
                int m = m0 + 4 * tr + i, n = 4 * tc + j;
                if (m < IDIM) Cp[(long long)m * NS + n] = acc[i][j];
            }
    } else if (bx < 392) {
        int b = bx - 384;
        int warp = tid >> 5, lane = tid & 31;
        for (int s = warp; s < NS; s += 8) {
            const float* r = slots + ((long long)b * NS + s) * SDIM;
            float acc = 0.f;
            for (int d = lane; d < SDIM; d += 32) acc += r[d];
            acc = wsum(acc);
            if (lane == 0) g_m[b * NS + s] = acc * (1.0f / SDIM);
        }
    } else {
        float (*ts)[129] = (float(*)[129])shbuf;
        int jd = bx - 392;
        int b = jd / 12;
        int d0 = (jd % 12) * 128;
        for (int idx = tid; idx < 64 * 128; idx += 256) {
            int s = idx >> 7, dd = idx & 127;
            ts[s][dd] = slots[((long long)b * NS + s) * SDIM + d0 + dd];
        }
        __syncthreads();
        for (int idx = tid; idx < 128 * 64; idx += 256) {
            int d = idx >> 6, s = idx & 63;
            float v = ts[s][d];
            __nv_bfloat16 h = __float2bfloat16(v);
            __nv_bfloat16 l = __float2bfloat16(v - __bfloat162float(h));
            long long o = ((long long)b * SDIM + d0 + d) * NS + s;
            g_sThi[o] = h;
            g_sTlo[o] = l;
        }
    }
}

// ---------------- finisher: reduce_G + reduce_T (coalesced) -----------------
__global__ void __launch_bounds__(256) prep_finish(float scale)
{
    __shared__ float ts[64][65];
    int bx = blockIdx.x;
    int tid = threadIdx.x;

    if (bx < 128) {
        int idx = bx * 256 + tid;
        int b = idx >> 12, r = idx & 4095;
        const float* p = g_Gpart + ((long long)b * 16) * (NS * NS) + r;
        float s = 0.f;
        #pragma unroll
        for (int k = 0; k < 16; ++k) s += p[(long long)k * (NS * NS)];
        g_G[(long long)b * (NS * NS) + r] = s;
    } else {
        int z = bx - 128;
        int b = z / 3, dg = z % 3;
        int dbase = dg * 64;
        int dcount = (dbase + 64 <= IDIM) ? 64 : (IDIM - dbase);
        const float* p = g_Tpart + (long long)b * 16 * (IDIM * NS) + (long long)dbase * NS;
        int nelem = dcount * NS;
        for (int e = 0; e < 16; ++e) {
            int idx = tid + 256 * e;
            if (idx < nelem) {
                float acc = 0.f;
                #pragma unroll
                for (int k = 0; k < 16; ++k) acc += p[(long long)k * (IDIM * NS) + idx];
                int dl = idx >> 6, s = idx & 63;
                ts[s][dl] = acc * scale;
            }
        }
        __syncthreads();
        float* outp = g_Tt + (long long)b * (NS * IDIM) + dbase;
        for (int o = tid; o < 64 * 64; o += 256) {
            int s = o >> 6, dl = o & 63;
            if (dl < dcount) outp[(long long)s * IDIM + dl] = ts[s][dl];
        }
    }
}

// ----------------- dots kernel: mma + x prefetch + w hi/lo emit -------------
#define DT_TTHI 0          // 64*200*2   = 25600
#define DT_TTLO 25600
#define DT_XNHI 51200      // 32*200*2   = 12800
#define DT_XNLO 64000
#define DT_DOTS 76800      // 32*68*4    = 8704  (dots, then w in-place)
#define DT_G    85504      // 64*68*4    = 17408
#define DT_M    102912     // 64*4
#define DT_G1   103168
#define DT_B1   103936
#define DOTS_SMEM_BYTES 104704

__global__ void __launch_bounds__(256) dots_kernel(
    const float* __restrict__ x, const float* __restrict__ g1v,
    const float* __restrict__ b1v, float* __restrict__ out_w)
{
    extern __shared__ char smc[];
    __nv_bfloat16* tthi = (__nv_bfloat16*)(smc + DT_TTHI);
    __nv_bfloat16* ttlo = (__nv_bfloat16*)(smc + DT_TTLO);
    __nv_bfloat16* xnhi = (__nv_bfloat16*)(smc + DT_XNHI);
    __nv_bfloat16* xnlo = (__nv_bfloat16*)(smc + DT_XNLO);
    float* dotsb = (float*)(smc + DT_DOTS);
    float* Gp    = (float*)(smc + DT_G);
    float* mP    = (float*)(smc + DT_M);
    float* g1P   = (float*)(smc + DT_G1);
    float* b1P   = (float*)(smc + DT_B1);

    int tid = threadIdx.x;
    int b = blockIdx.y;

    for (int i = tid; i < NS * 192; i += 256) {
        int s = i / 192, d = i % 192;
        float v = (d < IDIM) ? g_Tt[(long long)b * (NS * IDIM) + s * IDIM + d] : 0.f;
        __nv_bfloat16 h = __float2bfloat16(v);
        __nv_bfloat16 l = __float2bfloat16(v - __bfloat162float(h));
        tthi[s * 200 + d] = h;
        ttlo[s * 200 + d] = l;
    }
    for (int i = tid; i < NS * NS; i += 256) {
        int s = i >> 6, c = i & 63;
        Gp[s * 68 + c] = g_G[(long long)b * (NS * NS) + i];
    }
    if (tid < NS) mP[tid] = g_m[b * NS + tid];
    if (tid < IDIM) { g1P[tid] = g1v[tid]; b1P[tid] = b1v[tid]; }
    __syncthreads();

    int warp = tid >> 5, lane = tid & 31;
    uint32_t sbase = smem_u32(smc);

    int trow = lane & 15;
    uint32_t tq16 = (uint32_t)(lane >> 4) * 16;
    int mch = (warp & 1) * 16;
    int nbase = (warp >> 1) * 16;
    uint32_t arow_off = (uint32_t)(mch + trow) * 400 + tq16;
    uint32_t brow_off = (uint32_t)(nbase + ((lane >> 3) & 1) * 8 + (lane & 7)) * 400;

    long long blkrow = (long long)b * NI + (long long)blockIdx.x * 128;

    float xpre[4][6];
    {
        long long gbase = blkrow + warp * 4;
        #pragma unroll
        for (int j = 0; j < 4; ++j) {
            const float* xr = x + (gbase + j) * IDIM;
            #pragma unroll
            for (int t = 0; t < 6; ++t) {
                int d = lane + 32 * t;
                xpre[j][t] = (d < IDIM) ? xr[d] : 0.f;
            }
        }
    }

    for (int pass = 0; pass < 4; ++pass) {
        long long gblk = blkrow + pass * 32;
        long long gbase = gblk + warp * 4;

        #pragma unroll
        for (int j = 0; j < 4; ++j) {
            float s1 = 0.f, s2 = 0.f;
            #pragma unroll
            for (int t = 0; t < 6; ++t) {
                float v = xpre[j][t];
                s1 += v; s2 = fmaf(v, v, s2);
            }
            s1 = wsum(s1); s2 = wsum(s2);
            float mu = s1 * (1.0f / IDIM);
            float rs = rsqrtf(s2 * (1.0f / IDIM) - mu * mu + 1e-5f);
            int lrow = warp * 4 + j;
            #pragma unroll
            for (int t = 0; t < 6; ++t) {
                int d = lane + 32 * t;
                float v = (d < IDIM)
                    ? (xpre[j][t] - mu) * rs * g1P[d] + b1P[d] : 0.f;
                __nv_bfloat16 h = __float2bfloat16(v);
                __nv_bfloat16 l = __float2bfloat16(v - __bfloat162float(h));
                xnhi[lrow * 200 + d] = h;
                xnlo[lrow * 200 + d] = l;
            }
        }
        __syncthreads();   // S1

        {
            float c[2][4] = {};
            #pragma unroll
            for (int ks = 0; ks < 12; ++ks) {
                uint32_t kb = (uint32_t)ks * 32;
                uint32_t ah[4], al[4];
                uint32_t ra = sbase + DT_XNHI + arow_off + kb;
                ldm_x4(ra, ah);
                ldm_x4(ra + (DT_XNLO - DT_XNHI), al);
                uint32_t rb = sbase + DT_TTHI + brow_off + kb + tq16;
                uint32_t th[4], tl[4];
                ldm_x4(rb, th);
                ldm_x4(rb + (DT_TTLO - DT_TTHI), tl);
                uint32_t bh0[2] = {th[0], th[2]}, bh1[2] = {th[1], th[3]};
                uint32_t bl0[2] = {tl[0], tl[2]}, bl1[2] = {tl[1], tl[3]};
                mma_bf16(c[0], ah, bh0);
                mma_bf16(c[0], ah, bl0);
                mma_bf16(c[0], al, bh0);
                mma_bf16(c[1], ah, bh1);
                mma_bf16(c[1], ah, bl1);
                mma_bf16(c[1], al, bh1);
            }
            int r0 = mch + (lane >> 2);
            int col = nbase + 2 * (lane & 3);
            #pragma unroll
            for (int nt = 0; nt < 2; ++nt) {
                *(float2*)(dotsb + r0 * 68 + col + nt * 8)       = make_float2(c[nt][0], c[nt][1]);
                *(float2*)(dotsb + (r0 + 8) * 68 + col + nt * 8) = make_float2(c[nt][2], c[nt][3]);
            }
        }

        if (pass < 3) {
            long long gb2 = gblk + 32 + warp * 4;
            #pragma unroll
            for (int j = 0; j < 4; ++j) {
                const float* xr = x + (gb2 + j) * IDIM;
                #pragma unroll
                for (int t = 0; t < 6; ++t) {
                    int d = lane + 32 * t;
                    xpre[j][t] = (d < IDIM) ? xr[d] : 0.f;
                }
            }
        }
        __syncthreads();   // S2

        float w1a[4], w2a[4], mu2a[4];
        #pragma unroll
        for (int j = 0; j < 4; ++j) {
            int lrow = warp * 4 + j;
            float a0 = dotsb[lrow * 68 + lane];
            float a1 = dotsb[lrow * 68 + lane + 32];
            float mx = wmax(fmaxf(a0, a1));
            float e1 = __expf(a0 - mx), e2 = __expf(a1 - mx);
            float sum = wsum(e1 + e2);
            float inv = 1.0f / sum;
            float w1 = e1 * inv, w2 = e2 * inv;
            float* wo = out_w + (gbase + j) * NS;
            wo[lane] = w1; wo[lane + 32] = w2;
            // bf16 hi/lo for the tensor-core output GEMM
            __nv_bfloat16 h1 = __float2bfloat16(w1);
            __nv_bfloat16 h2 = __float2bfloat16(w2);
            long long wb = (gbase + j) * NS;
            g_whi[wb + lane] = h1;
            g_whi[wb + lane + 32] = h2;
            g_wlo[wb + lane] = __float2bfloat16(w1 - __bfloat162float(h1));
            g_wlo[wb + lane + 32] = __float2bfloat16(w2 - __bfloat162float(h2));
            dotsb[lrow * 68 + lane] = w1;
            dotsb[lrow * 68 + lane + 32] = w2;
            w1a[j] = w1; w2a[j] = w2;
            mu2a[j] = wsum(w1 * mP[lane] + w2 * mP[lane + 32]);
        }
        __syncwarp();

        {
            const float* gr0 = Gp + lane * 68;
            const float* gr1 = gr0 + 32 * 68;
            const float* wbase = dotsb + (warp * 4) * 68;
            ull GW1[4] = {0, 0, 0, 0}, GW2[4] = {0, 0, 0, 0};
            #pragma unroll 4
            for (int sp = 0; sp < NS; sp += 4) {
                ulonglong2 q0 = *(const ulonglong2*)(gr0 + sp);
                ulonglong2 q1 = *(const ulonglong2*)(gr1 + sp);
                #pragma unroll
                for (int j = 0; j < 4; ++j) {
                    ulonglong2 wv = *(const ulonglong2*)(wbase + j * 68 + sp);
                    GW1[j] = fma2(q0.x, wv.x, GW1[j]);
                    GW1[j] = fma2(q0.y, wv.y, GW1[j]);
                    GW2[j] = fma2(q1.x, wv.x, GW2[j]);
                    GW2[j] = fma2(q1.y, wv.y, GW2[j]);
                }
            }
            #pragma unroll
            for (int j = 0; j < 4; ++j) {
                float2 p1 = unpack2(GW1[j]), p2 = unpack2(GW2[j]);
                float gw1 = p1.x + p1.y, gw2 = p2.x + p2.y;
                float ssq = wsum(w1a[j] * gw1 + w2a[j] * gw2);
                float mu2 = mu2a[j];
                float rs2 = rsqrtf(ssq * (1.0f / SDIM) - mu2 * mu2 + 1e-5f);
                if (lane == 0) {
                    g_stats[gbase + j] = mu2;
                    g_stats[(long long)NB * NI + gbase + j] = rs2;
                }
            }
        }
        __syncthreads();   // S3
    }
}

// -------- mma.sync output GEMM: s = LN(w @ slots), 2 d-tiles per block ------
#define OM_SWHI 0
#define OM_SWLO 18432
#define OM_SSHI 36864
#define OM_SSLO 55296
#define OM_MU   73728
#define OM_RS   74240
#define OM_GAM  74752
#define OM_BET  75264
#define OM_BYTES 75776

__global__ void __launch_bounds__(256) out_mma_kernel(
    const float* __restrict__ g2v, const float* __restrict__ b2v,
    float* __restrict__ out_s)
{
    extern __shared__ char smc[];
    int tid = threadIdx.x;
    int b = blockIdx.z;
    int i0 = blockIdx.y * 128;
    long long gib = (long long)b * NI + i0;

    // fill w hi/lo + per-i stats once per block
    {
        const uint4* wh = (const uint4*)(g_whi + gib * NS);
        const uint4* wl = (const uint4*)(g_wlo + gib * NS);
        #pragma unroll
        for (int it = 0; it < 4; ++it) {
            int idx = tid + 256 * it;
            int r = idx >> 3, q = idx & 7;
            uint32_t doff = (uint32_t)r * 144 + (uint32_t)q * 16;
            *(uint4*)(smc + OM_SWHI + doff) = wh[idx];
            *(uint4*)(smc + OM_SWLO + doff) = wl[idx];
        }
        if (tid < 128) {
            ((float*)(smc + OM_MU))[tid] = g_stats[gib + tid];
            ((float*)(smc + OM_RS))[tid] = g_stats[(long long)NB * NI + gib + tid];
        }
    }

    int wid = tid >> 5, lane = tid & 31;
    int wm = wid & 3, wn = wid >> 2;
    uint32_t sbase = smem_u32(smc);
    int trow = lane & 15;
    uint32_t tcolb = (uint32_t)(lane >> 4) * 16;
    uint32_t brow = (uint32_t)(wn * 64 + ((lane >> 3) & 1) * 8 + (lane & 7)) * 144;
    uint32_t bcolbase = (uint32_t)(lane >> 4) * 16;
    const float* muP = (const float*)(smc + OM_MU);
    const float* rsP = (const float*)(smc + OM_RS);
    const float* gmP = (const float*)(smc + OM_GAM);
    const float* btP = (const float*)(smc + OM_BET);
    int grp = lane >> 2, tig = lane & 3;

    #pragma unroll 1
    for (int half = 0; half < 2; ++half) {
        int d0 = blockIdx.x * 256 + half * 128;
        if (half) __syncthreads();        // all warps done reading previous sT

        // fill sT hi/lo + gamma/beta for this d-tile
        {
            const uint4* sh = (const uint4*)(g_sThi + ((long long)b * SDIM + d0) * NS);
            const uint4* sl = (const uint4*)(g_sTlo + ((long long)b * SDIM + d0) * NS);
            #pragma unroll
            for (int it = 0; it < 4; ++it) {
                int idx = tid + 256 * it;
                int r = idx >> 3, q = idx & 7;
                uint32_t doff = (uint32_t)r * 144 + (uint32_t)q * 16;
                *(uint4*)(smc + OM_SSHI + doff) = sh[idx];
                *(uint4*)(smc + OM_SSLO + doff) = sl[idx];
            }
            if (tid < 128) {
                ((float*)(smc + OM_GAM))[tid] = g2v[d0 + tid];
                ((float*)(smc + OM_BET))[tid] = b2v[d0 + tid];
            }
        }
        __syncthreads();

        float c[2][8][4];
        #pragma unroll
        for (int mi = 0; mi < 2; ++mi)
            #pragma unroll
            for (int nj = 0; nj < 8; ++nj)
                #pragma unroll
                for (int q = 0; q < 4; ++q) c[mi][nj][q] = 0.f;

        #pragma unroll
        for (int ks = 0; ks < 4; ++ks) {
            uint32_t kb = (uint32_t)ks * 32 + tcolb;
            uint32_t ah[2][4], al[2][4];
            #pragma unroll
            for (int mi = 0; mi < 2; ++mi) {
                uint32_t ra = sbase + OM_SWHI + (uint32_t)(wm * 32 + mi * 16 + trow) * 144 + kb;
                ldm_x4(ra, ah[mi]);
                ldm_x4(ra + (OM_SWLO - OM_SWHI), al[mi]);
            }
            uint32_t bcol = (uint32_t)ks * 32 + bcolbase;
            #pragma unroll
            for (int g = 0; g < 4; ++g) {
                uint32_t rb = sbase + OM_SSHI + brow + (uint32_t)(g * 16) * 144 + bcol;
                uint32_t th[4], tl[4];
                ldm_x4(rb, th);
                ldm_x4(rb + (OM_SSLO - OM_SSHI), tl);
                uint32_t bh0[2] = {th[0], th[2]}, bh1[2] = {th[1], th[3]};
                uint32_t bl0[2] = {tl[0], tl[2]}, bl1[2] = {tl[1], tl[3]};
                #pragma unroll
                for (int mi = 0; mi < 2; ++mi) {
                    mma_bf16(c[mi][2 * g],     ah[mi], bh0);
                    mma_bf16(c[mi][2 * g],     ah[mi], bl0);
                    mma_bf16(c[mi][2 * g],     al[mi], bh0);
                    mma_bf16(c[mi][2 * g + 1], ah[mi], bh1);
                    mma_bf16(c[mi][2 * g + 1], ah[mi], bl1);
                    mma_bf16(c[mi][2 * g + 1], al[mi], bh1);
                }
            }
        }

        // epilogue: LN + store (registers + stats only — safe before next refill sync)
        #pragma unroll
        for (int mi = 0; mi < 2; ++mi) {
            int r0 = wm * 32 + mi * 16 + grp;
            int r1 = r0 + 8;
            float mu0 = muP[r0], rs0 = rsP[r0];
            float mu1 = muP[r1], rs1 = rsP[r1];
            #pragma unroll
            for (int nj = 0; nj < 8; ++nj) {
                int col = wn * 64 + nj * 8 + 2 * tig;
                float2 gm = *(const float2*)(gmP + col);
                float2 bt = *(const float2*)(btP + col);
                float* c4 = c[mi][nj];
                float2 v0, v1;
                v0.x = (c4[0] - mu0) * rs0 * gm.x + bt.x;
                v0.y = (c4[1] - mu0) * rs0 * gm.y + bt.y;
                v1.x = (c4[2] - mu1) * rs1 * gm.x + bt.x;
                v1.y = (c4[3] - mu1) * rs1 * gm.y + bt.y;
                *(float2*)(out_s + (gib + r0) * (long long)SDIM + d0 + col) = v0;
                *(float2*)(out_s + (gib + r1) * (long long)SDIM + d0 + col) = v1;
            }
        }
    }
}

// ------------------------------- launcher -----------------------------------
extern "C" void kernel_launch(void* const* d_in, const int* in_sizes, int n_in,
                              void* d_out, int out_size)
{
    const float* x     = (const float*)d_in[0];
    const float* slots = (const float*)d_in[1];
    const float* Wq    = (const float*)d_in[2];
    const float* Wk    = (const float*)d_in[3];
    const float* g1v   = (const float*)d_in[4];
    const float* b1v   = (const float*)d_in[5];
    const float* g2v   = (const float*)d_in[6];
    const float* b2v   = (const float*)d_in[7];

    float* out_s = (float*)d_out;
    float* out_w = out_s + (long long)NB * NI * SDIM;

    cudaFuncSetAttribute(dots_kernel, cudaFuncAttributeMaxDynamicSharedMemorySize, DOTS_SMEM_BYTES);
    cudaFuncSetAttribute(out_mma_kernel, cudaFuncAttributeMaxDynamicSharedMemorySize, OM_BYTES);

    float scale = (float)(1.0 / sqrt((double)ADIM));

    // 1) fused: M = Wq @ Wk^T (x8 split)  ||  G[b] = slots slots^T (x16 split)
    gemm_MG<<<704, 256>>>(Wq, Wk, slots);
    // 2) fused: T[b] = (sum Mpart) @ slots^T (x16 split) || slot means || split slots
    gemm_T_aux<<<488, 256>>>(slots);
    // 3) finishers: reduce G, reduce+scale+transpose T
    prep_finish<<<152, 256>>>(scale);
    // 4) dots via mma + softmax + LN2 stats + w fp32/bf16 emission
    dots_kernel<<<dim3(NI / 128, NB), 256, DOTS_SMEM_BYTES>>>(x, g1v, b1v, out_w);
    // 5) output GEMM + LN epilogue (2 d-tiles per block, w tile reused)
    out_mma_kernel<<<dim3(SDIM / 256, NI / 128, NB), 256, OM_BYTES>>>(g2v, b2v, out_s);
}

// round 16
// speedup vs baseline: 1.1324x; 1.1324x over previous
#include <cuda_runtime.h>
#include <cuda_bf16.h>
#include <cuda_fp16.h>
#include <cstdint>
#include <cmath>

typedef unsigned long long ull;

#define NB   8
#define NI   8192
#define IDIM 180
#define ADIM 1536
#define SDIM 1536
#define NS   64

// ----------------------------- device scratch -------------------------------
__device__ float g_Mpart[8 * IDIM * ADIM];
__device__ float g_Tpart[128 * IDIM * NS];
__device__ float g_Tt[NB * NS * IDIM];
__device__ float g_Gpart[128 * NS * NS];
__device__ float g_G[NB * NS * NS];
__device__ float g_m[NB * NS];
__device__ float g_stats[2 * NB * NI];
__device__ __align__(16) __half g_sThi[NB * SDIM * NS];   // slots^T hi fp16 [b][d][s]
__device__ __align__(16) __half g_sTlo[NB * SDIM * NS];   // slots^T lo fp16
__device__ __align__(16) __half g_wh[NB * NI * NS];       // w fp16 [b][i][s]

// ----------------------------- warp helpers ---------------------------------
__device__ __forceinline__ float wsum(float v) {
    #pragma unroll
    for (int o = 16; o > 0; o >>= 1) v += __shfl_xor_sync(0xffffffffu, v, o);
    return v;
}
__device__ __forceinline__ float wmax(float v) {
    #pragma unroll
    for (int o = 16; o > 0; o >>= 1) v = fmaxf(v, __shfl_xor_sync(0xffffffffu, v, o));
    return v;
}
__device__ __forceinline__ uint32_t smem_u32(const void* p) {
    uint32_t a;
    asm("{ .reg .u64 t; cvta.to.shared.u64 t, %1; cvt.u32.u64 %0, t; }" : "=r"(a) : "l"(p));
    return a;
}

// ----------------------------- f32x2 helpers ---------------------------------
__device__ __forceinline__ ull fma2(ull a, ull b, ull c) {
    ull d;
    asm("fma.rn.f32x2 %0, %1, %2, %3;" : "=l"(d) : "l"(a), "l"(b), "l"(c));
    return d;
}
__device__ __forceinline__ float2 unpack2(ull u) {
    float lo, hi;
    asm("mov.b64 {%0, %1}, %2;" : "=f"(lo), "=f"(hi) : "l"(u));
    return make_float2(lo, hi);
}

// --------------------------- mma.sync helpers --------------------------------
__device__ __forceinline__ void ldm_x4(uint32_t a, uint32_t* r) {
    asm volatile("ldmatrix.sync.aligned.m8n8.x4.shared.b16 {%0,%1,%2,%3}, [%4];"
        : "=r"(r[0]), "=r"(r[1]), "=r"(r[2]), "=r"(r[3]) : "r"(a));
}
__device__ __forceinline__ void mma_bf16(float* c, const uint32_t* a, const uint32_t* b) {
    asm volatile("mma.sync.aligned.m16n8k16.row.col.f32.bf16.bf16.f32 "
        "{%0,%1,%2,%3}, {%4,%5,%6,%7}, {%8,%9}, {%0,%1,%2,%3};"
        : "+f"(c[0]), "+f"(c[1]), "+f"(c[2]), "+f"(c[3])
        : "r"(a[0]), "r"(a[1]), "r"(a[2]), "r"(a[3]), "r"(b[0]), "r"(b[1]));
}
__device__ __forceinline__ void mma_f16(float* c, const uint32_t* a, const uint32_t* b) {
    asm volatile("mma.sync.aligned.m16n8k16.row.col.f32.f16.f16.f32 "
        "{%0,%1,%2,%3}, {%4,%5,%6,%7}, {%8,%9}, {%0,%1,%2,%3};"
        : "+f"(c[0]), "+f"(c[1]), "+f"(c[2]), "+f"(c[3])
        : "r"(a[0]), "r"(a[1]), "r"(a[2]), "r"(a[3]), "r"(b[0]), "r"(b[1]));
}

// ----------------------- shared GEMM tile body (NT) --------------------------
__device__ __forceinline__ void gemm_body(
    const float* __restrict__ A, const float* __restrict__ B, float* __restrict__ Cp,
    int M, int N, int Kchunk, int lda, int ldb, int m0, int n0,
    float (*As)[68], float (*Bs)[68])
{
    int tid = threadIdx.x;
    int tr = tid >> 4, tc = tid & 15;
    int lr = tid >> 2, lq = tid & 3;

    float acc[4][4] = {};

    for (int kb = 0; kb < Kchunk; kb += 16) {
        __syncthreads();
        float4 av = make_float4(0.f, 0.f, 0.f, 0.f);
        if (m0 + lr < M)
            av = *(const float4*)&A[(long long)(m0 + lr) * lda + kb + 4 * lq];
        As[4 * lq + 0][lr] = av.x; As[4 * lq + 1][lr] = av.y;
        As[4 * lq + 2][lr] = av.z; As[4 * lq + 3][lr] = av.w;
        float4 bv = make_float4(0.f, 0.f, 0.f, 0.f);
        if (n0 + lr < N)
            bv = *(const float4*)&B[(long long)(n0 + lr) * ldb + kb + 4 * lq];
        Bs[4 * lq + 0][lr] = bv.x; Bs[4 * lq + 1][lr] = bv.y;
        Bs[4 * lq + 2][lr] = bv.z; Bs[4 * lq + 3][lr] = bv.w;
        __syncthreads();
        #pragma unroll
        for (int k = 0; k < 16; ++k) {
            float4 a4 = *(const float4*)&As[k][4 * tr];
            float4 b4 = *(const float4*)&Bs[k][4 * tc];
            float a[4] = {a4.x, a4.y, a4.z, a4.w};
            float b[4] = {b4.x, b4.y, b4.z, b4.w};
            #pragma unroll
            for (int i = 0; i < 4; ++i)
                #pragma unroll
                for (int j = 0; j < 4; ++j)
                    acc[i][j] = fmaf(a[i], b[j], acc[i][j]);
        }
    }
    #pragma unroll
    for (int i = 0; i < 4; ++i)
        #pragma unroll
        for (int j = 0; j < 4; ++j) {
            int m = m0 + 4 * tr + i, n = n0 + 4 * tc + j;
            if (m < M && n < N) Cp[(long long)m * N + n] = acc[i][j];
        }
}

// ------------- fused M + G partial GEMMs (independent, one launch) ----------
__global__ void __launch_bounds__(256) gemm_MG(
    const float* __restrict__ Wq, const float* __restrict__ Wk,
    const float* __restrict__ slots)
{
    __shared__ __align__(16) float As[16][68];
    __shared__ __align__(16) float Bs[16][68];
    int bx = blockIdx.x;
    if (bx < 576) {
        int kk = bx & 7;
        int rem = bx >> 3;
        int mx = rem % 3, ny = rem / 3;
        gemm_body(Wq + kk * (ADIM / 8), Wk + kk * (ADIM / 8),
                  g_Mpart + (long long)kk * IDIM * ADIM,
                  IDIM, ADIM, ADIM / 8, ADIM, ADIM, mx * 64, ny * 64, As, Bs);
    } else {
        int z = bx - 576;
        int kk = z & 15, b = z >> 4;
        const float* sb = slots + (long long)b * NS * SDIM + kk * (SDIM / 16);
        gemm_body(sb, sb, g_Gpart + (long long)z * NS * NS,
                  NS, NS, SDIM / 16, SDIM, SDIM, 0, 0, As, Bs);
    }
}

// ---- T[b] = M @ slots^T (M summed inline from Mpart) + slot means + split --
__global__ void __launch_bounds__(256) gemm_T_aux(const float* __restrict__ slots)
{
    __shared__ __align__(16) char shbuf[33024];
    int bx = blockIdx.x;
    int tid = threadIdx.x;

    if (bx < 384) {
        int mx = bx % 3;
        int z = bx / 3;
        int kk = z & 15, b = z >> 4;
        int m0 = mx * 64;
        const float* B = slots + (long long)b * NS * SDIM + kk * (SDIM / 16);
        float* Cp = g_Tpart + (long long)z * IDIM * NS;
        float (*As)[68] = (float(*)[68])shbuf;
        float (*Bs)[68] = (float(*)[68])(shbuf + 4352);

        int tr = tid >> 4, tc = tid & 15;
        int lr = tid >> 2, lq = tid & 3;
        float acc[4][4] = {};

        for (int kb = 0; kb < SDIM / 16; kb += 16) {
            __syncthreads();
            float4 av = make_float4(0.f, 0.f, 0.f, 0.f);
            if (m0 + lr < IDIM) {
                const float* base = g_Mpart + (long long)(m0 + lr) * ADIM
                                  + kk * (SDIM / 16) + kb + 4 * lq;
                #pragma unroll
                for (int p = 0; p < 8; ++p) {
                    float4 v = *(const float4*)(base + (long long)p * IDIM * ADIM);
                    av.x += v.x; av.y += v.y; av.z += v.z; av.w += v.w;
                }
            }
            As[4 * lq + 0][lr] = av.x; As[4 * lq + 1][lr] = av.y;
            As[4 * lq + 2][lr] = av.z; As[4 * lq + 3][lr] = av.w;
            float4 bv = *(const float4*)&B[(long long)lr * SDIM + kb + 4 * lq];
            Bs[4 * lq + 0][lr] = bv.x; Bs[4 * lq + 1][lr] = bv.y;
            Bs[4 * lq + 2][lr] = bv.z; Bs[4 * lq + 3][lr] = bv.w;
            __syncthreads();
            #pragma unroll
            for (int k = 0; k < 16; ++k) {
                float4 a4 = *(const float4*)&As[k][4 * tr];
                float4 b4 = *(const float4*)&Bs[k][4 * tc];
                float a[4] = {a4.x, a4.y, a4.z, a4.w};
                float b[4] = {b4.x, b4.y, b4.z, b4.w};
                #pragma unroll
                for (int i = 0; i < 4; ++i)
                    #pragma unroll
                    for (int j = 0; j < 4; ++j)
                        acc[i][j] = fmaf(a[i], b[j], acc[i][j]);
            }
        }
        #pragma unroll
        for (int i = 0; i < 4; ++i)
            #pragma unroll
            for (int j = 0; j < 4; ++j) {
                int m = m0 + 4 * tr + i, n = 4 * tc + j;
                if (m < IDIM) Cp[(long long)m * NS + n] = acc[i][j];
            }
    } else if (bx < 392) {
        int b = bx - 384;
        int warp = tid >> 5, lane = tid & 31;
        for (int s = warp; s < NS; s += 8) {
            const float* r = slots + ((long long)b * NS + s) * SDIM;
            float acc = 0.f;
            for (int d = lane; d < SDIM; d += 32) acc += r[d];
            acc = wsum(acc);
            if (lane == 0) g_m[b * NS + s] = acc * (1.0f / SDIM);
        }
    } else {
        float (*ts)[129] = (float(*)[129])shbuf;
        int jd = bx - 392;
        int b = jd / 12;
        int d0 = (jd % 12) * 128;
        for (int idx = tid; idx < 64 * 128; idx += 256) {
            int s = idx >> 7, dd = idx & 127;
            ts[s][dd] = slots[((long long)b * NS + s) * SDIM + d0 + dd];
        }
        __syncthreads();
        for (int idx = tid; idx < 128 * 64; idx += 256) {
            int d = idx >> 6, s = idx & 63;
            float v = ts[s][d];
            __half h = __float2half_rn(v);
            __half l = __float2half_rn(v - __half2float(h));
            long long o = ((long long)b * SDIM + d0 + d) * NS + s;
            g_sThi[o] = h;
            g_sTlo[o] = l;
        }
    }
}

// ---------------- finisher: reduce_G + reduce_T (coalesced) -----------------
__global__ void __launch_bounds__(256) prep_finish(float scale)
{
    __shared__ float ts[64][65];
    int bx = blockIdx.x;
    int tid = threadIdx.x;

    if (bx < 128) {
        int idx = bx * 256 + tid;
        int b = idx >> 12, r = idx & 4095;
        const float* p = g_Gpart + ((long long)b * 16) * (NS * NS) + r;
        float s = 0.f;
        #pragma unroll
        for (int k = 0; k < 16; ++k) s += p[(long long)k * (NS * NS)];
        g_G[(long long)b * (NS * NS) + r] = s;
    } else {
        int z = bx - 128;
        int b = z / 3, dg = z % 3;
        int dbase = dg * 64;
        int dcount = (dbase + 64 <= IDIM) ? 64 : (IDIM - dbase);
        const float* p = g_Tpart + (long long)b * 16 * (IDIM * NS) + (long long)dbase * NS;
        int nelem = dcount * NS;
        for (int e = 0; e < 16; ++e) {
            int idx = tid + 256 * e;
            if (idx < nelem) {
                float acc = 0.f;
                #pragma unroll
                for (int k = 0; k < 16; ++k) acc += p[(long long)k * (IDIM * NS) + idx];
                int dl = idx >> 6, s = idx & 63;
                ts[s][dl] = acc * scale;
            }
        }
        __syncthreads();
        float* outp = g_Tt + (long long)b * (NS * IDIM) + dbase;
        for (int o = tid; o < 64 * 64; o += 256) {
            int s = o >> 6, dl = o & 63;
            if (dl < dcount) outp[(long long)s * IDIM + dl] = ts[s][dl];
        }
    }
}

// ----------------- dots kernel: mma + x prefetch + w fp16 emit --------------
#define DT_TTHI 0          // 64*200*2   = 25600
#define DT_TTLO 25600
#define DT_XNHI 51200      // 32*200*2   = 12800
#define DT_XNLO 64000
#define DT_DOTS 76800      // 32*68*4    = 8704  (dots, then w in-place)
#define DT_G    85504      // 64*68*4    = 17408
#define DT_M    102912     // 64*4
#define DT_G1   103168
#define DT_B1   103936
#define DOTS_SMEM_BYTES 104704

__global__ void __launch_bounds__(256) dots_kernel(
    const float* __restrict__ x, const float* __restrict__ g1v,
    const float* __restrict__ b1v, float* __restrict__ out_w)
{
    extern __shared__ char smc[];
    __nv_bfloat16* tthi = (__nv_bfloat16*)(smc + DT_TTHI);
    __nv_bfloat16* ttlo = (__nv_bfloat16*)(smc + DT_TTLO);
    __nv_bfloat16* xnhi = (__nv_bfloat16*)(smc + DT_XNHI);
    __nv_bfloat16* xnlo = (__nv_bfloat16*)(smc + DT_XNLO);
    float* dotsb = (float*)(smc + DT_DOTS);
    float* Gp    = (float*)(smc + DT_G);
    float* mP    = (float*)(smc + DT_M);
    float* g1P   = (float*)(smc + DT_G1);
    float* b1P   = (float*)(smc + DT_B1);

    int tid = threadIdx.x;
    int b = blockIdx.y;

    for (int i = tid; i < NS * 192; i += 256) {
        int s = i / 192, d = i % 192;
        float v = (d < IDIM) ? g_Tt[(long long)b * (NS * IDIM) + s * IDIM + d] : 0.f;
        __nv_bfloat16 h = __float2bfloat16(v);
        __nv_bfloat16 l = __float2bfloat16(v - __bfloat162float(h));
        tthi[s * 200 + d] = h;
        ttlo[s * 200 + d] = l;
    }
    for (int i = tid; i < NS * NS; i += 256) {
        int s = i >> 6, c = i & 63;
        Gp[s * 68 + c] = g_G[(long long)b * (NS * NS) + i];
    }
    if (tid < NS) mP[tid] = g_m[b * NS + tid];
    if (tid < IDIM) { g1P[tid] = g1v[tid]; b1P[tid] = b1v[tid]; }
    __syncthreads();

    int warp = tid >> 5, lane = tid & 31;
    uint32_t sbase = smem_u32(smc);

    int trow = lane & 15;
    uint32_t tq16 = (uint32_t)(lane >> 4) * 16;
    int mch = (warp & 1) * 16;
    int nbase = (warp >> 1) * 16;
    uint32_t arow_off = (uint32_t)(mch + trow) * 400 + tq16;
    uint32_t brow_off = (uint32_t)(nbase + ((lane >> 3) & 1) * 8 + (lane & 7)) * 400;

    long long blkrow = (long long)b * NI + (long long)blockIdx.x * 128;

    float xpre[4][6];
    {
        long long gbase = blkrow + warp * 4;
        #pragma unroll
        for (int j = 0; j < 4; ++j) {
            const float* xr = x + (gbase + j) * IDIM;
            #pragma unroll
            for (int t = 0; t < 6; ++t) {
                int d = lane + 32 * t;
                xpre[j][t] = (d < IDIM) ? xr[d] : 0.f;
            }
        }
    }

    for (int pass = 0; pass < 4; ++pass) {
        long long gblk = blkrow + pass * 32;
        long long gbase = gblk + warp * 4;

        #pragma unroll
        for (int j = 0; j < 4; ++j) {
            float s1 = 0.f, s2 = 0.f;
            #pragma unroll
            for (int t = 0; t < 6; ++t) {
                float v = xpre[j][t];
                s1 += v; s2 = fmaf(v, v, s2);
            }
            s1 = wsum(s1); s2 = wsum(s2);
            float mu = s1 * (1.0f / IDIM);
            float rs = rsqrtf(s2 * (1.0f / IDIM) - mu * mu + 1e-5f);
            int lrow = warp * 4 + j;
            #pragma unroll
            for (int t = 0; t < 6; ++t) {
                int d = lane + 32 * t;
                float v = (d < IDIM)
                    ? (xpre[j][t] - mu) * rs * g1P[d] + b1P[d] : 0.f;
                __nv_bfloat16 h = __float2bfloat16(v);
                __nv_bfloat16 l = __float2bfloat16(v - __bfloat162float(h));
                xnhi[lrow * 200 + d] = h;
                xnlo[lrow * 200 + d] = l;
            }
        }
        __syncthreads();   // S1

        {
            float c[2][4] = {};
            #pragma unroll
            for (int ks = 0; ks < 12; ++ks) {
                uint32_t kb = (uint32_t)ks * 32;
                uint32_t ah[4], al[4];
                uint32_t ra = sbase + DT_XNHI + arow_off + kb;
                ldm_x4(ra, ah);
                ldm_x4(ra + (DT_XNLO - DT_XNHI), al);
                uint32_t rb = sbase + DT_TTHI + brow_off + kb + tq16;
                uint32_t th[4], tl[4];
                ldm_x4(rb, th);
                ldm_x4(rb + (DT_TTLO - DT_TTHI), tl);
                uint32_t bh0[2] = {th[0], th[2]}, bh1[2] = {th[1], th[3]};
                uint32_t bl0[2] = {tl[0], tl[2]}, bl1[2] = {tl[1], tl[3]};
                mma_bf16(c[0], ah, bh0);
                mma_bf16(c[0], ah, bl0);
                mma_bf16(c[0], al, bh0);
                mma_bf16(c[1], ah, bh1);
                mma_bf16(c[1], ah, bl1);
                mma_bf16(c[1], al, bh1);
            }
            int r0 = mch + (lane >> 2);
            int col = nbase + 2 * (lane & 3);
            #pragma unroll
            for (int nt = 0; nt < 2; ++nt) {
                *(float2*)(dotsb + r0 * 68 + col + nt * 8)       = make_float2(c[nt][0], c[nt][1]);
                *(float2*)(dotsb + (r0 + 8) * 68 + col + nt * 8) = make_float2(c[nt][2], c[nt][3]);
            }
        }

        if (pass < 3) {
            long long gb2 = gblk + 32 + warp * 4;
            #pragma unroll
            for (int j = 0; j < 4; ++j) {
                const float* xr = x + (gb2 + j) * IDIM;
                #pragma unroll
                for (int t = 0; t < 6; ++t) {
                    int d = lane + 32 * t;
                    xpre[j][t] = (d < IDIM) ? xr[d] : 0.f;
                }
            }
        }
        __syncthreads();   // S2

        float w1a[4], w2a[4], mu2a[4];
        #pragma unroll
        for (int j = 0; j < 4; ++j) {
            int lrow = warp * 4 + j;
            float a0 = dotsb[lrow * 68 + lane];
            float a1 = dotsb[lrow * 68 + lane + 32];
            float mx = wmax(fmaxf(a0, a1));
            float e1 = __expf(a0 - mx), e2 = __expf(a1 - mx);
            float sum = wsum(e1 + e2);
            float inv = 1.0f / sum;
            float w1 = e1 * inv, w2 = e2 * inv;
            float* wo = out_w + (gbase + j) * NS;
            wo[lane] = w1; wo[lane + 32] = w2;
            // fp16 copy for the output GEMM
            long long wb = (gbase + j) * NS;
            g_wh[wb + lane] = __float2half_rn(w1);
            g_wh[wb + lane + 32] = __float2half_rn(w2);
            dotsb[lrow * 68 + lane] = w1;
            dotsb[lrow * 68 + lane + 32] = w2;
            w1a[j] = w1; w2a[j] = w2;
            mu2a[j] = wsum(w1 * mP[lane] + w2 * mP[lane + 32]);
        }
        __syncwarp();

        {
            const float* gr0 = Gp + lane * 68;
            const float* gr1 = gr0 + 32 * 68;
            const float* wbase = dotsb + (warp * 4) * 68;
            ull GW1[4] = {0, 0, 0, 0}, GW2[4] = {0, 0, 0, 0};
            #pragma unroll 4
            for (int sp = 0; sp < NS; sp += 4) {
                ulonglong2 q0 = *(const ulonglong2*)(gr0 + sp);
                ulonglong2 q1 = *(const ulonglong2*)(gr1 + sp);
                #pragma unroll
                for (int j = 0; j < 4; ++j) {
                    ulonglong2 wv = *(const ulonglong2*)(wbase + j * 68 + sp);
                    GW1[j] = fma2(q0.x, wv.x, GW1[j]);
                    GW1[j] = fma2(q0.y, wv.y, GW1[j]);
                    GW2[j] = fma2(q1.x, wv.x, GW2[j]);
                    GW2[j] = fma2(q1.y, wv.y, GW2[j]);
                }
            }
            #pragma unroll
            for (int j = 0; j < 4; ++j) {
                float2 p1 = unpack2(GW1[j]), p2 = unpack2(GW2[j]);
                float gw1 = p1.x + p1.y, gw2 = p2.x + p2.y;
                float ssq = wsum(w1a[j] * gw1 + w2a[j] * gw2);
                float mu2 = mu2a[j];
                float rs2 = rsqrtf(ssq * (1.0f / SDIM) - mu2 * mu2 + 1e-5f);
                if (lane == 0) {
                    g_stats[gbase + j] = mu2;
                    g_stats[(long long)NB * NI + gbase + j] = rs2;
                }
            }
        }
        __syncthreads();   // S3
    }
}

// ------- fp16 2-term mma.sync output GEMM: s = LN(w @ slots) ----------------
// Tile 128 i x 128 d per block. Terms: w_f16 * sThi + w_f16 * sTlo.
#define OF_W   0        // 128*144 = 18432
#define OF_SH  18432
#define OF_SL  36864
#define OF_MU  55296
#define OF_RS  55808
#define OF_GAM 56320
#define OF_BET 56832
#define OF_BYTES 57344

__global__ void __launch_bounds__(256) out_mma_kernel(
    const float* __restrict__ g2v, const float* __restrict__ b2v,
    float* __restrict__ out_s)
{
    extern __shared__ char smc[];
    int tid = threadIdx.x;
    int b = blockIdx.z;
    int i0 = blockIdx.y * 128;
    int d0 = blockIdx.x * 128;
    long long gib = (long long)b * NI + i0;

    const uint4* wp = (const uint4*)(g_wh + gib * NS);
    const uint4* sh = (const uint4*)(g_sThi + ((long long)b * SDIM + d0) * NS);
    const uint4* sl = (const uint4*)(g_sTlo + ((long long)b * SDIM + d0) * NS);
    #pragma unroll
    for (int it = 0; it < 4; ++it) {
        int idx = tid + 256 * it;            // 1024 uint4 per operand
        int r = idx >> 3, q = idx & 7;
        uint32_t doff = (uint32_t)r * 144 + (uint32_t)q * 16;
        *(uint4*)(smc + OF_W + doff)  = wp[idx];
        *(uint4*)(smc + OF_SH + doff) = sh[idx];
        *(uint4*)(smc + OF_SL + doff) = sl[idx];
    }
    if (tid < 128) {
        ((float*)(smc + OF_MU))[tid]  = g_stats[gib + tid];
        ((float*)(smc + OF_RS))[tid]  = g_stats[(long long)NB * NI + gib + tid];
        ((float*)(smc + OF_GAM))[tid] = g2v[d0 + tid];
        ((float*)(smc + OF_BET))[tid] = b2v[d0 + tid];
    }
    __syncthreads();

    int wid = tid >> 5, lane = tid & 31;
    int wm = wid & 3, wn = wid >> 2;      // warp tile: 32 i x 64 d
    uint32_t sbase = smem_u32(smc);
    int trow = lane & 15;
    uint32_t tcolb = (uint32_t)(lane >> 4) * 16;

    float c[2][8][4];
    #pragma unroll
    for (int mi = 0; mi < 2; ++mi)
        #pragma unroll
        for (int nj = 0; nj < 8; ++nj)
            #pragma unroll
            for (int q = 0; q < 4; ++q) c[mi][nj][q] = 0.f;

    uint32_t brow = (uint32_t)(wn * 64 + ((lane >> 3) & 1) * 8 + (lane & 7)) * 144;
    uint32_t bcolbase = (uint32_t)(lane >> 4) * 16;

    #pragma unroll
    for (int ks = 0; ks < 4; ++ks) {
        uint32_t kb = (uint32_t)ks * 32 + tcolb;
        uint32_t aw[2][4];
        #pragma unroll
        for (int mi = 0; mi < 2; ++mi) {
            uint32_t ra = sbase + OF_W + (uint32_t)(wm * 32 + mi * 16 + trow) * 144 + kb;
            ldm_x4(ra, aw[mi]);
        }
        uint32_t bcol = (uint32_t)ks * 32 + bcolbase;
        #pragma unroll
        for (int g = 0; g < 4; ++g) {
            uint32_t rb = sbase + OF_SH + brow + (uint32_t)(g * 16) * 144 + bcol;
            uint32_t th[4], tl[4];
            ldm_x4(rb, th);
            ldm_x4(rb + (OF_SL - OF_SH), tl);
            uint32_t bh0[2] = {th[0], th[2]}, bh1[2] = {th[1], th[3]};
            uint32_t bl0[2] = {tl[0], tl[2]}, bl1[2] = {tl[1], tl[3]};
            #pragma unroll
            for (int mi = 0; mi < 2; ++mi) {
                mma_f16(c[mi][2 * g],     aw[mi], bh0);
                mma_f16(c[mi][2 * g],     aw[mi], bl0);
                mma_f16(c[mi][2 * g + 1], aw[mi], bh1);
                mma_f16(c[mi][2 * g + 1], aw[mi], bl1);
            }
        }
    }

    const float* muP = (const float*)(smc + OF_MU);
    const float* rsP = (const float*)(smc + OF_RS);
    const float* gmP = (const float*)(smc + OF_GAM);
    const float* btP = (const float*)(smc + OF_BET);
    int grp = lane >> 2, tig = lane & 3;
    #pragma unroll
    for (int mi = 0; mi < 2; ++mi) {
        int r0 = wm * 32 + mi * 16 + grp;
        int r1 = r0 + 8;
        float mu0 = muP[r0], rs0 = rsP[r0];
        float mu1 = muP[r1], rs1 = rsP[r1];
        #pragma unroll
        for (int nj = 0; nj < 8; ++nj) {
            int col = wn * 64 + nj * 8 + 2 * tig;
            float2 gm = *(const float2*)(gmP + col);
            float2 bt = *(const float2*)(btP + col);
            float* c4 = c[mi][nj];
            float2 v0, v1;
            v0.x = (c4[0] - mu0) * rs0 * gm.x + bt.x;
            v0.y = (c4[1] - mu0) * rs0 * gm.y + bt.y;
            v1.x = (c4[2] - mu1) * rs1 * gm.x + bt.x;
            v1.y = (c4[3] - mu1) * rs1 * gm.y + bt.y;
            *(float2*)(out_s + (gib + r0) * (long long)SDIM + d0 + col) = v0;
            *(float2*)(out_s + (gib + r1) * (long long)SDIM + d0 + col) = v1;
        }
    }
}

// ------------------------------- launcher -----------------------------------
extern "C" void kernel_launch(void* const* d_in, const int* in_sizes, int n_in,
                              void* d_out, int out_size)
{
    const float* x     = (const float*)d_in[0];
    const float* slots = (const float*)d_in[1];
    const float* Wq    = (const float*)d_in[2];
    const float* Wk    = (const float*)d_in[3];
    const float* g1v   = (const float*)d_in[4];
    const float* b1v   = (const float*)d_in[5];
    const float* g2v   = (const float*)d_in[6];
    const float* b2v   = (const float*)d_in[7];

    float* out_s = (float*)d_out;
    float* out_w = out_s + (long long)NB * NI * SDIM;

    cudaFuncSetAttribute(dots_kernel, cudaFuncAttributeMaxDynamicSharedMemorySize, DOTS_SMEM_BYTES);
    cudaFuncSetAttribute(out_mma_kernel, cudaFuncAttributeMaxDynamicSharedMemorySize, OF_BYTES);

    float scale = (float)(1.0 / sqrt((double)ADIM));

    // 1) fused: M = Wq @ Wk^T (x8 split)  ||  G[b] = slots slots^T (x16 split)
    gemm_MG<<<704, 256>>>(Wq, Wk, slots);
    // 2) fused: T[b] = (sum Mpart) @ slots^T (x16 split) || slot means || split slots (fp16)
    gemm_T_aux<<<488, 256>>>(slots);
    // 3) finishers: reduce G, reduce+scale+transpose T
    prep_finish<<<152, 256>>>(scale);
    // 4) dots via mma + softmax + LN2 stats + w fp32/fp16 emission
    dots_kernel<<<dim3(NI / 128, NB), 256, DOTS_SMEM_BYTES>>>(x, g1v, b1v, out_w);
    // 5) output GEMM fp16 2-term + LN epilogue
    out_mma_kernel<<<dim3(SDIM / 128, NI / 128, NB), 256, OF_BYTES>>>(g2v, b2v, out_s);
}

// round 17
// speedup vs baseline: 1.2133x; 1.0714x over previous
#include <cuda_runtime.h>
#include <cuda_bf16.h>
#include <cuda_fp16.h>
#include <cstdint>
#include <cmath>

typedef unsigned long long ull;

#define NB   8
#define NI   8192
#define IDIM 180
#define ADIM 1536
#define SDIM 1536
#define NS   64

// ----------------------------- device scratch -------------------------------
__device__ float g_Mpart[8 * IDIM * ADIM];
__device__ float g_Tpart[128 * IDIM * NS];
__device__ float g_Tt[NB * NS * IDIM];
__device__ float g_Gpart[128 * NS * NS];
__device__ float g_G[NB * NS * NS];
__device__ float g_m[NB * NS];
__device__ float g_stats[2 * NB * NI];
__device__ __align__(16) __half g_sT[NB * SDIM * NS];    // slots^T fp16 [b][d][s]
__device__ __align__(16) __half g_wh[NB * NI * NS];      // w fp16 [b][i][s]

// ----------------------------- warp helpers ---------------------------------
__device__ __forceinline__ float wsum(float v) {
    #pragma unroll
    for (int o = 16; o > 0; o >>= 1) v += __shfl_xor_sync(0xffffffffu, v, o);
    return v;
}
__device__ __forceinline__ float wmax(float v) {
    #pragma unroll
    for (int o = 16; o > 0; o >>= 1) v = fmaxf(v, __shfl_xor_sync(0xffffffffu, v, o));
    return v;
}
__device__ __forceinline__ uint32_t smem_u32(const void* p) {
    uint32_t a;
    asm("{ .reg .u64 t; cvta.to.shared.u64 t, %1; cvt.u32.u64 %0, t; }" : "=r"(a) : "l"(p));
    return a;
}

// ----------------------------- f32x2 helpers ---------------------------------
__device__ __forceinline__ ull fma2(ull a, ull b, ull c) {
    ull d;
    asm("fma.rn.f32x2 %0, %1, %2, %3;" : "=l"(d) : "l"(a), "l"(b), "l"(c));
    return d;
}
__device__ __forceinline__ float2 unpack2(ull u) {
    float lo, hi;
    asm("mov.b64 {%0, %1}, %2;" : "=f"(lo), "=f"(hi) : "l"(u));
    return make_float2(lo, hi);
}

// --------------------------- mma.sync helpers --------------------------------
__device__ __forceinline__ void ldm_x4(uint32_t a, uint32_t* r) {
    asm volatile("ldmatrix.sync.aligned.m8n8.x4.shared.b16 {%0,%1,%2,%3}, [%4];"
        : "=r"(r[0]), "=r"(r[1]), "=r"(r[2]), "=r"(r[3]) : "r"(a));
}
__device__ __forceinline__ void mma_bf16(float* c, const uint32_t* a, const uint32_t* b) {
    asm volatile("mma.sync.aligned.m16n8k16.row.col.f32.bf16.bf16.f32 "
        "{%0,%1,%2,%3}, {%4,%5,%6,%7}, {%8,%9}, {%0,%1,%2,%3};"
        : "+f"(c[0]), "+f"(c[1]), "+f"(c[2]), "+f"(c[3])
        : "r"(a[0]), "r"(a[1]), "r"(a[2]), "r"(a[3]), "r"(b[0]), "r"(b[1]));
}
__device__ __forceinline__ void mma_f16(float* c, const uint32_t* a, const uint32_t* b) {
    asm volatile("mma.sync.aligned.m16n8k16.row.col.f32.f16.f16.f32 "
        "{%0,%1,%2,%3}, {%4,%5,%6,%7}, {%8,%9}, {%0,%1,%2,%3};"
        : "+f"(c[0]), "+f"(c[1]), "+f"(c[2]), "+f"(c[3])
        : "r"(a[0]), "r"(a[1]), "r"(a[2]), "r"(a[3]), "r"(b[0]), "r"(b[1]));
}

// ----------------------- shared GEMM tile body (NT) --------------------------
__device__ __forceinline__ void gemm_body(
    const float* __restrict__ A, const float* __restrict__ B, float* __restrict__ Cp,
    int M, int N, int Kchunk, int lda, int ldb, int m0, int n0,
    float (*As)[68], float (*Bs)[68])
{
    int tid = threadIdx.x;
    int tr = tid >> 4, tc = tid & 15;
    int lr = tid >> 2, lq = tid & 3;

    float acc[4][4] = {};

    for (int kb = 0; kb < Kchunk; kb += 16) {
        __syncthreads();
        float4 av = make_float4(0.f, 0.f, 0.f, 0.f);
        if (m0 + lr < M)
            av = *(const float4*)&A[(long long)(m0 + lr) * lda + kb + 4 * lq];
        As[4 * lq + 0][lr] = av.x; As[4 * lq + 1][lr] = av.y;
        As[4 * lq + 2][lr] = av.z; As[4 * lq + 3][lr] = av.w;
        float4 bv = make_float4(0.f, 0.f, 0.f, 0.f);
        if (n0 + lr < N)
            bv = *(const float4*)&B[(long long)(n0 + lr) * ldb + kb + 4 * lq];
        Bs[4 * lq + 0][lr] = bv.x; Bs[4 * lq + 1][lr] = bv.y;
        Bs[4 * lq + 2][lr] = bv.z; Bs[4 * lq + 3][lr] = bv.w;
        __syncthreads();
        #pragma unroll
        for (int k = 0; k < 16; ++k) {
            float4 a4 = *(const float4*)&As[k][4 * tr];
            float4 b4 = *(const float4*)&Bs[k][4 * tc];
            float a[4] = {a4.x, a4.y, a4.z, a4.w};
            float b[4] = {b4.x, b4.y, b4.z, b4.w};
            #pragma unroll
            for (int i = 0; i < 4; ++i)
                #pragma unroll
                for (int j = 0; j < 4; ++j)
                    acc[i][j] = fmaf(a[i], b[j], acc[i][j]);
        }
    }
    #pragma unroll
    for (int i = 0; i < 4; ++i)
        #pragma unroll
        for (int j = 0; j < 4; ++j) {
            int m = m0 + 4 * tr + i, n = n0 + 4 * tc + j;
            if (m < M && n < N) Cp[(long long)m * N + n] = acc[i][j];
        }
}

// ------------- fused M + G partial GEMMs (independent, one launch) ----------
__global__ void __launch_bounds__(256) gemm_MG(
    const float* __restrict__ Wq, const float* __restrict__ Wk,
    const float* __restrict__ slots)
{
    __shared__ __align__(16) float As[16][68];
    __shared__ __align__(16) float Bs[16][68];
    int bx = blockIdx.x;
    if (bx < 576) {
        int kk = bx & 7;
        int rem = bx >> 3;
        int mx = rem % 3, ny = rem / 3;
        gemm_body(Wq + kk * (ADIM / 8), Wk + kk * (ADIM / 8),
                  g_Mpart + (long long)kk * IDIM * ADIM,
                  IDIM, ADIM, ADIM / 8, ADIM, ADIM, mx * 64, ny * 64, As, Bs);
    } else {
        int z = bx - 576;
        int kk = z & 15, b = z >> 4;
        const float* sb = slots + (long long)b * NS * SDIM + kk * (SDIM / 16);
        gemm_body(sb, sb, g_Gpart + (long long)z * NS * NS,
                  NS, NS, SDIM / 16, SDIM, SDIM, 0, 0, As, Bs);
    }
}

// ---- T[b] = M @ slots^T (M summed inline from Mpart) + slot means + split --
__global__ void __launch_bounds__(256) gemm_T_aux(const float* __restrict__ slots)
{
    __shared__ __align__(16) char shbuf[33024];
    int bx = blockIdx.x;
    int tid = threadIdx.x;

    if (bx < 384) {
        int mx = bx % 3;
        int z = bx / 3;
        int kk = z & 15, b = z >> 4;
        int m0 = mx * 64;
        const float* B = slots + (long long)b * NS * SDIM + kk * (SDIM / 16);
        float* Cp = g_Tpart + (long long)z * IDIM * NS;
        float (*As)[68] = (float(*)[68])shbuf;
        float (*Bs)[68] = (float(*)[68])(shbuf + 4352);

        int tr = tid >> 4, tc = tid & 15;
        int lr = tid >> 2, lq = tid & 3;
        float acc[4][4] = {};

        for (int kb = 0; kb < SDIM / 16; kb += 16) {
            __syncthreads();
            float4 av = make_float4(0.f, 0.f, 0.f, 0.f);
            if (m0 + lr < IDIM) {
                const float* base = g_Mpart + (long long)(m0 + lr) * ADIM
                                  + kk * (SDIM / 16) + kb + 4 * lq;
                #pragma unroll
                for (int p = 0; p < 8; ++p) {
                    float4 v = *(const float4*)(base + (long long)p * IDIM * ADIM);
                    av.x += v.x; av.y += v.y; av.z += v.z; av.w += v.w;
                }
            }
            As[4 * lq + 0][lr] = av.x; As[4 * lq + 1][lr] = av.y;
            As[4 * lq + 2][lr] = av.z; As[4 * lq + 3][lr] = av.w;
            float4 bv = *(const float4*)&B[(long long)lr * SDIM + kb + 4 * lq];
            Bs[4 * lq + 0][lr] = bv.x; Bs[4 * lq + 1][lr] = bv.y;
            Bs[4 * lq + 2][lr] = bv.z; Bs[4 * lq + 3][lr] = bv.w;
            __syncthreads();
            #pragma unroll
            for (int k = 0; k < 16; ++k) {
                float4 a4 = *(const float4*)&As[k][4 * tr];
                float4 b4 = *(const float4*)&Bs[k][4 * tc];
                float a[4] = {a4.x, a4.y, a4.z, a4.w};
                float b[4] = {b4.x, b4.y, b4.z, b4.w};
                #pragma unroll
                for (int i = 0; i < 4; ++i)
                    #pragma unroll
                    for (int j = 0; j < 4; ++j)
                        acc[i][j] = fmaf(a[i], b[j], acc[i][j]);
            }
        }
        #pragma unroll
        for (int i = 0; i < 4; ++i)
            #pragma unroll
            for (int j = 0; j < 4; ++j) {
                int m = m0 + 4 * tr + i, n = 4 * tc + j;
                if (m < IDIM) Cp[(long long)m * NS + n] = acc[i][j];
            }
    } else if (bx < 392) {
        int b = bx - 384;
        int warp = tid >> 5, lane = tid & 31;
        for (int s = warp; s < NS; s += 8) {
            const float* r = slots + ((long long)b * NS + s) * SDIM;
            float acc = 0.f;
            for (int d = lane; d < SDIM; d += 32) acc += r[d];
            acc = wsum(acc);
            if (lane == 0) g_m[b * NS + s] = acc * (1.0f / SDIM);
        }
    } else {
        float (*ts)[129] = (float(*)[129])shbuf;
        int jd = bx - 392;
        int b = jd / 12;
        int d0 = (jd % 12) * 128;
        for (int idx = tid; idx < 64 * 128; idx += 256) {
            int s = idx >> 7, dd = idx & 127;
            ts[s][dd] = slots[((long long)b * NS + s) * SDIM + d0 + dd];
        }
        __syncthreads();
        for (int idx = tid; idx < 128 * 64; idx += 256) {
            int d = idx >> 6, s = idx & 63;
            long long o = ((long long)b * SDIM + d0 + d) * NS + s;
            g_sT[o] = __float2half_rn(ts[s][d]);
        }
    }
}

// ---------------- finisher: reduce_G + reduce_T (coalesced) -----------------
__global__ void __launch_bounds__(256) prep_finish(float scale)
{
    __shared__ float ts[64][65];
    int bx = blockIdx.x;
    int tid = threadIdx.x;

    if (bx < 128) {
        int idx = bx * 256 + tid;
        int b = idx >> 12, r = idx & 4095;
        const float* p = g_Gpart + ((long long)b * 16) * (NS * NS) + r;
        float s = 0.f;
        #pragma unroll
        for (int k = 0; k < 16; ++k) s += p[(long long)k * (NS * NS)];
        g_G[(long long)b * (NS * NS) + r] = s;
    } else {
        int z = bx - 128;
        int b = z / 3, dg = z % 3;
        int dbase = dg * 64;
        int dcount = (dbase + 64 <= IDIM) ? 64 : (IDIM - dbase);
        const float* p = g_Tpart + (long long)b * 16 * (IDIM * NS) + (long long)dbase * NS;
        int nelem = dcount * NS;
        for (int e = 0; e < 16; ++e) {
            int idx = tid + 256 * e;
            if (idx < nelem) {
                float acc = 0.f;
                #pragma unroll
                for (int k = 0; k < 16; ++k) acc += p[(long long)k * (IDIM * NS) + idx];
                int dl = idx >> 6, s = idx & 63;
                ts[s][dl] = acc * scale;
            }
        }
        __syncthreads();
        float* outp = g_Tt + (long long)b * (NS * IDIM) + dbase;
        for (int o = tid; o < 64 * 64; o += 256) {
            int s = o >> 6, dl = o & 63;
            if (dl < dcount) outp[(long long)s * IDIM + dl] = ts[s][dl];
        }
    }
}

// ----------------- dots kernel: mma + x prefetch + w fp16 emit --------------
#define DT_TTHI 0          // 64*200*2   = 25600
#define DT_TTLO 25600
#define DT_XNHI 51200      // 32*200*2   = 12800
#define DT_XNLO 64000
#define DT_DOTS 76800      // 32*68*4    = 8704  (dots, then w in-place)
#define DT_G    85504      // 64*68*4    = 17408
#define DT_M    102912     // 64*4
#define DT_G1   103168
#define DT_B1   103936
#define DOTS_SMEM_BYTES 104704

__global__ void __launch_bounds__(256) dots_kernel(
    const float* __restrict__ x, const float* __restrict__ g1v,
    const float* __restrict__ b1v, float* __restrict__ out_w)
{
    extern __shared__ char smc[];
    __nv_bfloat16* tthi = (__nv_bfloat16*)(smc + DT_TTHI);
    __nv_bfloat16* ttlo = (__nv_bfloat16*)(smc + DT_TTLO);
    __nv_bfloat16* xnhi = (__nv_bfloat16*)(smc + DT_XNHI);
    __nv_bfloat16* xnlo = (__nv_bfloat16*)(smc + DT_XNLO);
    float* dotsb = (float*)(smc + DT_DOTS);
    float* Gp    = (float*)(smc + DT_G);
    float* mP    = (float*)(smc + DT_M);
    float* g1P   = (float*)(smc + DT_G1);
    float* b1P   = (float*)(smc + DT_B1);

    int tid = threadIdx.x;
    int b = blockIdx.y;

    for (int i = tid; i < NS * 192; i += 256) {
        int s = i / 192, d = i % 192;
        float v = (d < IDIM) ? g_Tt[(long long)b * (NS * IDIM) + s * IDIM + d] : 0.f;
        __nv_bfloat16 h = __float2bfloat16(v);
        __nv_bfloat16 l = __float2bfloat16(v - __bfloat162float(h));
        tthi[s * 200 + d] = h;
        ttlo[s * 200 + d] = l;
    }
    for (int i = tid; i < NS * NS; i += 256) {
        int s = i >> 6, c = i & 63;
        Gp[s * 68 + c] = g_G[(long long)b * (NS * NS) + i];
    }
    if (tid < NS) mP[tid] = g_m[b * NS + tid];
    if (tid < IDIM) { g1P[tid] = g1v[tid]; b1P[tid] = b1v[tid]; }
    __syncthreads();

    int warp = tid >> 5, lane = tid & 31;
    uint32_t sbase = smem_u32(smc);

    int trow = lane & 15;
    uint32_t tq16 = (uint32_t)(lane >> 4) * 16;
    int mch = (warp & 1) * 16;
    int nbase = (warp >> 1) * 16;
    uint32_t arow_off = (uint32_t)(mch + trow) * 400 + tq16;
    uint32_t brow_off = (uint32_t)(nbase + ((lane >> 3) & 1) * 8 + (lane & 7)) * 400;

    long long blkrow = (long long)b * NI + (long long)blockIdx.x * 128;

    float xpre[4][6];
    {
        long long gbase = blkrow + warp * 4;
        #pragma unroll
        for (int j = 0; j < 4; ++j) {
            const float* xr = x + (gbase + j) * IDIM;
            #pragma unroll
            for (int t = 0; t < 6; ++t) {
                int d = lane + 32 * t;
                xpre[j][t] = (d < IDIM) ? xr[d] : 0.f;
            }
        }
    }

    for (int pass = 0; pass < 4; ++pass) {
        long long gblk = blkrow + pass * 32;
        long long gbase = gblk + warp * 4;

        #pragma unroll
        for (int j = 0; j < 4; ++j) {
            float s1 = 0.f, s2 = 0.f;
            #pragma unroll
            for (int t = 0; t < 6; ++t) {
                float v = xpre[j][t];
                s1 += v; s2 = fmaf(v, v, s2);
            }
            s1 = wsum(s1); s2 = wsum(s2);
            float mu = s1 * (1.0f / IDIM);
            float rs = rsqrtf(s2 * (1.0f / IDIM) - mu * mu + 1e-5f);
            int lrow = warp * 4 + j;
            #pragma unroll
            for (int t = 0; t < 6; ++t) {
                int d = lane + 32 * t;
                float v = (d < IDIM)
                    ? (xpre[j][t] - mu) * rs * g1P[d] + b1P[d] : 0.f;
                __nv_bfloat16 h = __float2bfloat16(v);
                __nv_bfloat16 l = __float2bfloat16(v - __bfloat162float(h));
                xnhi[lrow * 200 + d] = h;
                xnlo[lrow * 200 + d] = l;
            }
        }
        __syncthreads();   // S1

        {
            float c[2][4] = {};
            #pragma unroll
            for (int ks = 0; ks < 12; ++ks) {
                uint32_t kb = (uint32_t)ks * 32;
                uint32_t ah[4], al[4];
                uint32_t ra = sbase + DT_XNHI + arow_off + kb;
                ldm_x4(ra, ah);
                ldm_x4(ra + (DT_XNLO - DT_XNHI), al);
                uint32_t rb = sbase + DT_TTHI + brow_off + kb + tq16;
                uint32_t th[4], tl[4];
                ldm_x4(rb, th);
                ldm_x4(rb + (DT_TTLO - DT_TTHI), tl);
                uint32_t bh0[2] = {th[0], th[2]}, bh1[2] = {th[1], th[3]};
                uint32_t bl0[2] = {tl[0], tl[2]}, bl1[2] = {tl[1], tl[3]};
                mma_bf16(c[0], ah, bh0);
                mma_bf16(c[0], ah, bl0);
                mma_bf16(c[0], al, bh0);
                mma_bf16(c[1], ah, bh1);
                mma_bf16(c[1], ah, bl1);
                mma_bf16(c[1], al, bh1);
            }
            int r0 = mch + (lane >> 2);
            int col = nbase + 2 * (lane & 3);
            #pragma unroll
            for (int nt = 0; nt < 2; ++nt) {
                *(float2*)(dotsb + r0 * 68 + col + nt * 8)       = make_float2(c[nt][0], c[nt][1]);
                *(float2*)(dotsb + (r0 + 8) * 68 + col + nt * 8) = make_float2(c[nt][2], c[nt][3]);
            }
        }

        if (pass < 3) {
            long long gb2 = gblk + 32 + warp * 4;
            #pragma unroll
            for (int j = 0; j < 4; ++j) {
                const float* xr = x + (gb2 + j) * IDIM;
                #pragma unroll
                for (int t = 0; t < 6; ++t) {
                    int d = lane + 32 * t;
                    xpre[j][t] = (d < IDIM) ? xr[d] : 0.f;
                }
            }
        }
        __syncthreads();   // S2

        float w1a[4], w2a[4], mu2a[4];
        #pragma unroll
        for (int j = 0; j < 4; ++j) {
            int lrow = warp * 4 + j;
            float a0 = dotsb[lrow * 68 + lane];
            float a1 = dotsb[lrow * 68 + lane + 32];
            float mx = wmax(fmaxf(a0, a1));
            float e1 = __expf(a0 - mx), e2 = __expf(a1 - mx);
            float sum = wsum(e1 + e2);
            float inv = 1.0f / sum;
            float w1 = e1 * inv, w2 = e2 * inv;
            float* wo = out_w + (gbase + j) * NS;
            wo[lane] = w1; wo[lane + 32] = w2;
            long long wb = (gbase + j) * NS;
            g_wh[wb + lane] = __float2half_rn(w1);
            g_wh[wb + lane + 32] = __float2half_rn(w2);
            dotsb[lrow * 68 + lane] = w1;
            dotsb[lrow * 68 + lane + 32] = w2;
            w1a[j] = w1; w2a[j] = w2;
            mu2a[j] = wsum(w1 * mP[lane] + w2 * mP[lane + 32]);
        }
        __syncwarp();

        {
            const float* gr0 = Gp + lane * 68;
            const float* gr1 = gr0 + 32 * 68;
            const float* wbase = dotsb + (warp * 4) * 68;
            ull GW1[4] = {0, 0, 0, 0}, GW2[4] = {0, 0, 0, 0};
            #pragma unroll 4
            for (int sp = 0; sp < NS; sp += 4) {
                ulonglong2 q0 = *(const ulonglong2*)(gr0 + sp);
                ulonglong2 q1 = *(const ulonglong2*)(gr1 + sp);
                #pragma unroll
                for (int j = 0; j < 4; ++j) {
                    ulonglong2 wv = *(const ulonglong2*)(wbase + j * 68 + sp);
                    GW1[j] = fma2(q0.x, wv.x, GW1[j]);
                    GW1[j] = fma2(q0.y, wv.y, GW1[j]);
                    GW2[j] = fma2(q1.x, wv.x, GW2[j]);
                    GW2[j] = fma2(q1.y, wv.y, GW2[j]);
                }
            }
            #pragma unroll
            for (int j = 0; j < 4; ++j) {
                float2 p1 = unpack2(GW1[j]), p2 = unpack2(GW2[j]);
                float gw1 = p1.x + p1.y, gw2 = p2.x + p2.y;
                float ssq = wsum(w1a[j] * gw1 + w2a[j] * gw2);
                float mu2 = mu2a[j];
                float rs2 = rsqrtf(ssq * (1.0f / SDIM) - mu2 * mu2 + 1e-5f);
                if (lane == 0) {
                    g_stats[gbase + j] = mu2;
                    g_stats[(long long)NB * NI + gbase + j] = rs2;
                }
            }
        }
        __syncthreads();   // S3
    }
}

// ------- fp16 1-term mma.sync output GEMM: s = LN(w @ slots) ----------------
// Tile 128 i x 128 d per block. s ~= w_f16 * sT_f16, fp32 accumulate.
#define OF_W   0        // 128*144 = 18432
#define OF_S   18432
#define OF_MU  36864
#define OF_RS  37376
#define OF_GAM 37888
#define OF_BET 38400
#define OF_BYTES 38912

__global__ void __launch_bounds__(256) out_mma_kernel(
    const float* __restrict__ g2v, const float* __restrict__ b2v,
    float* __restrict__ out_s)
{
    extern __shared__ char smc[];
    int tid = threadIdx.x;
    int b = blockIdx.z;
    int i0 = blockIdx.y * 128;
    int d0 = blockIdx.x * 128;
    long long gib = (long long)b * NI + i0;

    const uint4* wp = (const uint4*)(g_wh + gib * NS);
    const uint4* sp = (const uint4*)(g_sT + ((long long)b * SDIM + d0) * NS);
    #pragma unroll
    for (int it = 0; it < 4; ++it) {
        int idx = tid + 256 * it;            // 1024 uint4 per operand
        int r = idx >> 3, q = idx & 7;
        uint32_t doff = (uint32_t)r * 144 + (uint32_t)q * 16;
        *(uint4*)(smc + OF_W + doff) = wp[idx];
        *(uint4*)(smc + OF_S + doff) = sp[idx];
    }
    if (tid < 128) {
        ((float*)(smc + OF_MU))[tid]  = g_stats[gib + tid];
        ((float*)(smc + OF_RS))[tid]  = g_stats[(long long)NB * NI + gib + tid];
        ((float*)(smc + OF_GAM))[tid] = g2v[d0 + tid];
        ((float*)(smc + OF_BET))[tid] = b2v[d0 + tid];
    }
    __syncthreads();

    int wid = tid >> 5, lane = tid & 31;
    int wm = wid & 3, wn = wid >> 2;      // warp tile: 32 i x 64 d
    uint32_t sbase = smem_u32(smc);
    int trow = lane & 15;
    uint32_t tcolb = (uint32_t)(lane >> 4) * 16;

    float c[2][8][4];
    #pragma unroll
    for (int mi = 0; mi < 2; ++mi)
        #pragma unroll
        for (int nj = 0; nj < 8; ++nj)
            #pragma unroll
            for (int q = 0; q < 4; ++q) c[mi][nj][q] = 0.f;

    uint32_t brow = (uint32_t)(wn * 64 + ((lane >> 3) & 1) * 8 + (lane & 7)) * 144;
    uint32_t bcolbase = (uint32_t)(lane >> 4) * 16;

    #pragma unroll
    for (int ks = 0; ks < 4; ++ks) {
        uint32_t kb = (uint32_t)ks * 32 + tcolb;
        uint32_t aw[2][4];
        #pragma unroll
        for (int mi = 0; mi < 2; ++mi) {
            uint32_t ra = sbase + OF_W + (uint32_t)(wm * 32 + mi * 16 + trow) * 144 + kb;
            ldm_x4(ra, aw[mi]);
        }
        uint32_t bcol = (uint32_t)ks * 32 + bcolbase;
        #pragma unroll
        for (int g = 0; g < 4; ++g) {
            uint32_t rb = sbase + OF_S + brow + (uint32_t)(g * 16) * 144 + bcol;
            uint32_t th[4];
            ldm_x4(rb, th);
            uint32_t bh0[2] = {th[0], th[2]}, bh1[2] = {th[1], th[3]};
            #pragma unroll
            for (int mi = 0; mi < 2; ++mi) {
                mma_f16(c[mi][2 * g],     aw[mi], bh0);
                mma_f16(c[mi][2 * g + 1], aw[mi], bh1);
            }
        }
    }

    const float* muP = (const float*)(smc + OF_MU);
    const float* rsP = (const float*)(smc + OF_RS);
    const float* gmP = (const float*)(smc + OF_GAM);
    const float* btP = (const float*)(smc + OF_BET);
    int grp = lane >> 2, tig = lane & 3;
    #pragma unroll
    for (int mi = 0; mi < 2; ++mi) {
        int r0 = wm * 32 + mi * 16 + grp;
        int r1 = r0 + 8;
        float mu0 = muP[r0], rs0 = rsP[r0];
        float mu1 = muP[r1], rs1 = rsP[r1];
        #pragma unroll
        for (int nj = 0; nj < 8; ++nj) {
            int col = wn * 64 + nj * 8 + 2 * tig;
            float2 gm = *(const float2*)(gmP + col);
            float2 bt = *(const float2*)(btP + col);
            float* c4 = c[mi][nj];
            float2 v0, v1;
            v0.x = (c4[0] - mu0) * rs0 * gm.x + bt.x;
            v0.y = (c4[1] - mu0) * rs0 * gm.y + bt.y;
            v1.x = (c4[2] - mu1) * rs1 * gm.x + bt.x;
            v1.y = (c4[3] - mu1) * rs1 * gm.y + bt.y;
            *(float2*)(out_s + (gib + r0) * (long long)SDIM + d0 + col) = v0;
            *(float2*)(out_s + (gib + r1) * (long long)SDIM + d0 + col) = v1;
        }
    }
}

// ------------------------------- launcher -----------------------------------
extern "C" void kernel_launch(void* const* d_in, const int* in_sizes, int n_in,
                              void* d_out, int out_size)
{
    const float* x     = (const float*)d_in[0];
    const float* slots = (const float*)d_in[1];
    const float* Wq    = (const float*)d_in[2];
    const float* Wk    = (const float*)d_in[3];
    const float* g1v   = (const float*)d_in[4];
    const float* b1v   = (const float*)d_in[5];
    const float* g2v   = (const float*)d_in[6];
    const float* b2v   = (const float*)d_in[7];

    float* out_s = (float*)d_out;
    float* out_w = out_s + (long long)NB * NI * SDIM;

    cudaFuncSetAttribute(dots_kernel, cudaFuncAttributeMaxDynamicSharedMemorySize, DOTS_SMEM_BYTES);
    cudaFuncSetAttribute(out_mma_kernel, cudaFuncAttributeMaxDynamicSharedMemorySize, OF_BYTES);

    float scale = (float)(1.0 / sqrt((double)ADIM));

    // 1) fused: M = Wq @ Wk^T (x8 split)  ||  G[b] = slots slots^T (x16 split)
    gemm_MG<<<704, 256>>>(Wq, Wk, slots);
    // 2) fused: T[b] = (sum Mpart) @ slots^T (x16 split) || slot means || slots^T fp16
    gemm_T_aux<<<488, 256>>>(slots);
    // 3) finishers: reduce G, reduce+scale+transpose T
    prep_finish<<<152, 256>>>(scale);
    // 4) dots via mma + softmax + LN2 stats + w fp32/fp16 emission
    dots_kernel<<<dim3(NI / 128, NB), 256, DOTS_SMEM_BYTES>>>(x, g1v, b1v, out_w);
    // 5) output GEMM fp16 1-term + LN epilogue
    out_mma_kernel<<<dim3(SDIM / 128, NI / 128, NB), 256, OF_BYTES>>>(g2v, b2v, out_s);
}